// round 12
// baseline (speedup 1.0000x reference)
#include <cuda_runtime.h>
#include <cuda_bf16.h>
#include <math.h>

#define N      6144
#define F      512
#define H      4
#define FH     64
#define HF     256   // H*FH
#define C      40
#define MAXD   256
#define ALPHA  0.2f

// ---------------- device scratch ----------------
__device__ float g_Wh1[N * HF];
__device__ float g_f1[H * N];
__device__ float g_f2[H * N];
__device__ float g_h[N * HF];
__device__ int   g_nbr[N * MAXD];
__device__ int   g_deg[N];
__device__ float g_Wh2[N * C];
__device__ float g_f1o[N];
__device__ float g_f2o[N];

// ================= gemm1: Wh1 = x @ Wcat via 3xTF32 tensor-core MMA ======
// Block tile 128x64, 8 warps 4(M)x2(N), warp tile 32x32.
// tf32 hi/lo split precomputed ONCE at smem-tile load time.
#define GBM 128
#define GBN 64
#define GBK 32
#define SPAD 36   // row stride in words: conflict-free fragment loads

// dynamic smem layout (uint words)
#define OFF_AHI 0
#define OFF_ALO (GBM * SPAD)
#define OFF_BHI (2 * GBM * SPAD)
#define OFF_BLO (2 * GBM * SPAD + GBN * SPAD)
#define SMEM_WORDS (2 * GBM * SPAD + 2 * GBN * SPAD)
#define SMEM_BYTES (SMEM_WORDS * 4)

__device__ __forceinline__ void split_tf32(float v, unsigned& hi, unsigned& lo) {
    asm("cvt.rna.tf32.f32 %0, %1;" : "=r"(hi) : "f"(v));
    float r = v - __uint_as_float(hi);
    asm("cvt.rna.tf32.f32 %0, %1;" : "=r"(lo) : "f"(r));
}

#define MMA_TF32(d, a, b)                                                     \
    asm volatile(                                                             \
        "mma.sync.aligned.m16n8k8.row.col.f32.tf32.tf32.f32 "                 \
        "{%0,%1,%2,%3}, {%4,%5,%6,%7}, {%8,%9}, {%0,%1,%2,%3};"               \
        : "+f"(d[0]), "+f"(d[1]), "+f"(d[2]), "+f"(d[3])                      \
        : "r"(a[0]), "r"(a[1]), "r"(a[2]), "r"(a[3]), "r"(b[0]), "r"(b[1]))

__global__ __launch_bounds__(256) void gemm1_tc(const float* __restrict__ x,
                                                const float* __restrict__ W) {
    extern __shared__ unsigned dsm[];
    unsigned* As_hi = dsm + OFF_AHI;
    unsigned* As_lo = dsm + OFF_ALO;
    unsigned* Bs_hi = dsm + OFF_BHI;
    unsigned* Bs_lo = dsm + OFF_BLO;

    const int tid = threadIdx.x;
    const int wid = tid >> 5, lane = tid & 31;
    const int group = lane >> 2, tig = lane & 3;
    const int warp_m = wid >> 1, warp_n = wid & 1;
    const int row0 = blockIdx.y * GBM;
    const int col0 = blockIdx.x * GBN;           // one head per block col
    const float* Wb = W + (col0 >> 6) * (F * FH);

    float acc[2][4][4];
#pragma unroll
    for (int mt = 0; mt < 2; mt++)
#pragma unroll
        for (int nt = 0; nt < 4; nt++)
#pragma unroll
            for (int j = 0; j < 4; j++) acc[mt][nt][j] = 0.f;

    for (int k0 = 0; k0 < F; k0 += GBK) {
        // A tile: 128 rows x 32 k, split at load
#pragma unroll
        for (int it = 0; it < 4; it++) {
            int idx = tid + it * 256;
            int m = idx >> 3, q = idx & 7;
            float4 v = *(const float4*)&x[(row0 + m) * F + k0 + q * 4];
            unsigned hi, lo;
            split_tf32(v.x, hi, lo); As_hi[m * SPAD + q * 4 + 0] = hi; As_lo[m * SPAD + q * 4 + 0] = lo;
            split_tf32(v.y, hi, lo); As_hi[m * SPAD + q * 4 + 1] = hi; As_lo[m * SPAD + q * 4 + 1] = lo;
            split_tf32(v.z, hi, lo); As_hi[m * SPAD + q * 4 + 2] = hi; As_lo[m * SPAD + q * 4 + 2] = lo;
            split_tf32(v.w, hi, lo); As_hi[m * SPAD + q * 4 + 3] = hi; As_lo[m * SPAD + q * 4 + 3] = lo;
        }
        // B tile: 32 k x 64 c, transposed [n][k], split at load
#pragma unroll
        for (int it = 0; it < 2; it++) {
            int idx = tid + it * 256;
            int k = idx >> 4, cq = idx & 15;
            float4 v = *(const float4*)&Wb[(k0 + k) * FH + cq * 4];
            unsigned hi, lo;
            split_tf32(v.x, hi, lo); Bs_hi[(cq * 4 + 0) * SPAD + k] = hi; Bs_lo[(cq * 4 + 0) * SPAD + k] = lo;
            split_tf32(v.y, hi, lo); Bs_hi[(cq * 4 + 1) * SPAD + k] = hi; Bs_lo[(cq * 4 + 1) * SPAD + k] = lo;
            split_tf32(v.z, hi, lo); Bs_hi[(cq * 4 + 2) * SPAD + k] = hi; Bs_lo[(cq * 4 + 2) * SPAD + k] = lo;
            split_tf32(v.w, hi, lo); Bs_hi[(cq * 4 + 3) * SPAD + k] = hi; Bs_lo[(cq * 4 + 3) * SPAD + k] = lo;
        }
        __syncthreads();
#pragma unroll
        for (int kk = 0; kk < 4; kk++) {
            const int kb = kk * 8;
            unsigned ahi[2][4], alo[2][4];
#pragma unroll
            for (int mt = 0; mt < 2; mt++) {
                int r0i = (warp_m * 32 + mt * 16 + group) * SPAD + kb + tig;
                int r1i = r0i + 8 * SPAD;
                ahi[mt][0] = As_hi[r0i];     alo[mt][0] = As_lo[r0i];
                ahi[mt][1] = As_hi[r1i];     alo[mt][1] = As_lo[r1i];
                ahi[mt][2] = As_hi[r0i + 4]; alo[mt][2] = As_lo[r0i + 4];
                ahi[mt][3] = As_hi[r1i + 4]; alo[mt][3] = As_lo[r1i + 4];
            }
            unsigned bhi[4][2], blo[4][2];
#pragma unroll
            for (int nt = 0; nt < 4; nt++) {
                int ni = (warp_n * 32 + nt * 8 + group) * SPAD + kb + tig;
                bhi[nt][0] = Bs_hi[ni];     blo[nt][0] = Bs_lo[ni];
                bhi[nt][1] = Bs_hi[ni + 4]; blo[nt][1] = Bs_lo[ni + 4];
            }
#pragma unroll
            for (int mt = 0; mt < 2; mt++)
#pragma unroll
                for (int nt = 0; nt < 4; nt++) {
                    MMA_TF32(acc[mt][nt], ahi[mt], bhi[nt]);
                    MMA_TF32(acc[mt][nt], alo[mt], bhi[nt]);
                    MMA_TF32(acc[mt][nt], ahi[mt], blo[nt]);
                }
        }
        __syncthreads();
    }
#pragma unroll
    for (int mt = 0; mt < 2; mt++)
#pragma unroll
        for (int nt = 0; nt < 4; nt++) {
            int r = row0 + warp_m * 32 + mt * 16 + group;
            int cc = col0 + warp_n * 32 + nt * 8 + tig * 2;
            float2 v0 = {acc[mt][nt][0], acc[mt][nt][1]};
            float2 v1 = {acc[mt][nt][2], acc[mt][nt][3]};
            *(float2*)&g_Wh1[r * HF + cc] = v0;
            *(float2*)&g_Wh1[(r + 8) * HF + cc] = v1;
        }
}

// ---------------- scores1 ------------------------------------------------
__global__ void scores1_kernel(const float* __restrict__ a1,
                               const float* __restrict__ a2) {
    int idx = blockIdx.x * blockDim.x + threadIdx.x;
    if (idx >= N * H) return;
    int i = idx >> 2;
    int h = idx & 3;
    const float* wh = &g_Wh1[i * HF + h * FH];
    float s1 = 0.f, s2 = 0.f;
#pragma unroll
    for (int c = 0; c < FH; c++) {
        float v = wh[c];
        s1 += v * a1[h * FH + c];
        s2 += v * a2[h * FH + c];
    }
    g_f1[h * N + i] = s1;
    g_f2[h * N + i] = s2;
}

// ---------------- build CSR ----------------------------------------------
__global__ void build_csr_kernel(const float* __restrict__ adj) {
    int warp = (blockIdx.x * blockDim.x + threadIdx.x) >> 5;
    int lane = threadIdx.x & 31;
    if (warp >= N) return;
    const float* row = adj + (long long)warp * N;
    int cnt = 0;
    for (int j0 = 0; j0 < N; j0 += 32) {
        float v = row[j0 + lane];
        unsigned m = __ballot_sync(0xffffffffu, v > 0.f);
        if (v > 0.f) {
            int pre = __popc(m & ((1u << lane) - 1u));
            int slot = cnt + pre;
            if (slot < MAXD) g_nbr[warp * MAXD + slot] = j0 + lane;
        }
        cnt += __popc(m);
    }
    if (lane == 0) g_deg[warp] = cnt < MAXD ? cnt : MAXD;
}

// ---------------- agg1: layer-1 softmax aggregation + ELU ----------------
// Phases 1-2 (softmax weights): 64 lanes per head, cooperative.
// Phase 3 (gather): 4 groups x 64 threads, each group takes every-4th
// neighbor with float4 row loads; cross-group reduction in smem.
__global__ __launch_bounds__(256) void agg1_kernel(void) {
    const int i = blockIdx.x;
    const int t = threadIdx.x;
    const int h = t >> 6, c = t & 63;
    const int lane = t & 31;
    const int half = (t >> 5) & 1;

    __shared__ int   s_nbr[MAXD];
    __shared__ float s_w[H][MAXD];
    __shared__ float s_red[H][2];
    __shared__ float s_sum[H][2];
    __shared__ float s_sumf[H];
    __shared__ float s_part[4 * HF];

    const int deg = g_deg[i];
    for (int k = t; k < deg; k += 256) s_nbr[k] = g_nbr[i * MAXD + k];
    __syncthreads();

    const float f1 = g_f1[h * N + i];

    float lmax = -3.0e38f;
    for (int k = c; k < deg; k += 64) {
        float s = f1 + g_f2[h * N + s_nbr[k]];
        s = s > 0.f ? s : ALPHA * s;
        s_w[h][k] = s;
        lmax = fmaxf(lmax, s);
    }
#pragma unroll
    for (int o = 16; o > 0; o >>= 1)
        lmax = fmaxf(lmax, __shfl_xor_sync(0xffffffffu, lmax, o));
    if (lane == 0) s_red[h][half] = lmax;
    __syncthreads();
    const float mx = fmaxf(s_red[h][0], s_red[h][1]);

    float lsum = 0.f;
    for (int k = c; k < deg; k += 64) {
        float w = expf(s_w[h][k] - mx);
        s_w[h][k] = w;
        lsum += w;
    }
#pragma unroll
    for (int o = 16; o > 0; o >>= 1)
        lsum += __shfl_xor_sync(0xffffffffu, lsum, o);
    if (lane == 0) s_sum[h][half] = lsum;
    __syncthreads();
    if (c == 0) s_sumf[h] = s_sum[h][0] + s_sum[h][1];

    // ---- gather: group g handles neighbors k = g, g+4, ... with float4 ----
    const int g = t >> 6;       // group
    const int u = t & 63;       // float4 index within the 256-col row
    const int h2 = u >> 4;      // head owning columns u*4..u*4+3
    float ax = 0.f, ay = 0.f, az = 0.f, aw = 0.f;
#pragma unroll 4
    for (int k = g; k < deg; k += 4) {
        float w = s_w[h2][k];
        float4 v = __ldg((const float4*)(g_Wh1 + s_nbr[k] * HF) + u);
        ax += w * v.x; ay += w * v.y; az += w * v.z; aw += w * v.w;
    }
    // conflict-free component-major store: s_part[g*256 + j*64 + u]
    s_part[g * HF + 0 * 64 + u] = ax;
    s_part[g * HF + 1 * 64 + u] = ay;
    s_part[g * HF + 2 * 64 + u] = az;
    s_part[g * HF + 3 * 64 + u] = aw;
    __syncthreads();

    // thread t finalizes column t
    const int cu = t >> 2, cj = t & 3;
    float v = s_part[0 * HF + cj * 64 + cu] + s_part[1 * HF + cj * 64 + cu] +
              s_part[2 * HF + cj * 64 + cu] + s_part[3 * HF + cj * 64 + cu];
    v /= s_sumf[t >> 6];
    v = v > 0.f ? v : expm1f(v);
    g_h[i * HF + t] = v;
}

// ------- gemm2 + scores2 fused: Wh2 = h @ Wo; f1o/f2o per row ------------
#define G2R 32
__global__ __launch_bounds__(256) void gemm2_kernel(const float* __restrict__ Wo,
                                                    const float* __restrict__ ao1,
                                                    const float* __restrict__ ao2) {
    __shared__ float sh[G2R][HF + 4];
    __shared__ float s_o[G2R][C + 4];
    const int i0 = blockIdx.x * G2R;
    const int tid = threadIdx.x;

#pragma unroll
    for (int it = 0; it < 8; it++) {
        int idx = tid + it * 256;
        int r = idx >> 6, kq = idx & 63;
        float4 v = *(const float4*)&g_h[(i0 + r) * HF + kq * 4];
        *(float4*)&sh[r][kq * 4] = v;
    }
    __syncthreads();

    if (tid < 160) {
        int cc = tid % 40;
        int rg = tid / 40;              // 0..3, 8 rows each
        float acc[8];
#pragma unroll
        for (int j = 0; j < 8; j++) acc[j] = 0.f;
        for (int k = 0; k < HF; k++) {
            float wv = __ldg(&Wo[k * C + cc]);
#pragma unroll
            for (int j = 0; j < 8; j++)
                acc[j] += wv * sh[rg * 8 + j][k];
        }
#pragma unroll
        for (int j = 0; j < 8; j++) {
            g_Wh2[(i0 + rg * 8 + j) * C + cc] = acc[j];
            s_o[rg * 8 + j][cc] = acc[j];
        }
    }
    __syncthreads();

    if (tid < G2R) {
        float s1 = 0.f, s2 = 0.f;
#pragma unroll
        for (int cc = 0; cc < C; cc++) {
            float v = s_o[tid][cc];
            s1 += v * ao1[cc];
            s2 += v * ao2[cc];
        }
        g_f1o[i0 + tid] = s1;
        g_f2o[i0 + tid] = s2;
    }
}

// -------- agg2: layer-2 aggregation + ELU + log_softmax ------------------
__global__ __launch_bounds__(64) void agg2_kernel(float* __restrict__ out) {
    const int i = blockIdx.x;
    const int t = threadIdx.x;          // 64 threads, 2 warps
    const int lane = t & 31, w = t >> 5;
    __shared__ int   s_nbr[MAXD];
    __shared__ float s_w[MAXD];
    __shared__ float s_r[2];
    __shared__ float red[64];

    const int deg = g_deg[i];
    const float f1 = g_f1o[i];

    float lmax = -3.0e38f;
    for (int k = t; k < deg; k += 64) {
        int j = g_nbr[i * MAXD + k];
        s_nbr[k] = j;
        float s = f1 + g_f2o[j];
        s = s > 0.f ? s : ALPHA * s;
        s_w[k] = s;
        lmax = fmaxf(lmax, s);
    }
#pragma unroll
    for (int o = 16; o > 0; o >>= 1)
        lmax = fmaxf(lmax, __shfl_xor_sync(0xffffffffu, lmax, o));
    if (lane == 0) s_r[w] = lmax;
    __syncthreads();
    const float mx = fmaxf(s_r[0], s_r[1]);

    float lsum = 0.f;
    for (int k = t; k < deg; k += 64) {
        float e = expf(s_w[k] - mx);
        s_w[k] = e;
        lsum += e;
    }
#pragma unroll
    for (int o = 16; o > 0; o >>= 1)
        lsum += __shfl_xor_sync(0xffffffffu, lsum, o);
    __syncthreads();
    if (lane == 0) s_r[w] = lsum;
    __syncthreads();
    const float sum = s_r[0] + s_r[1];

    float acc = 0.f;
    if (t < C) {
        for (int k = 0; k < deg; k++)
            acc += s_w[k] * g_Wh2[s_nbr[k] * C + t];
    }
    float v = acc / sum;
    v = v > 0.f ? v : expm1f(v);

    red[t] = (t < C) ? v : -3.0e38f;
    __syncthreads();
#pragma unroll
    for (int s = 32; s > 0; s >>= 1) {
        if (t < s) red[t] = fmaxf(red[t], red[t + s]);
        __syncthreads();
    }
    float m2 = red[0];
    __syncthreads();
    red[t] = (t < C) ? expf(v - m2) : 0.f;
    __syncthreads();
#pragma unroll
    for (int s = 32; s > 0; s >>= 1) {
        if (t < s) red[t] += red[t + s];
        __syncthreads();
    }
    float lse = m2 + logf(red[0]);
    if (t < C) out[i * C + t] = v - lse;
}

// ---------------- launch ---------------------------------------------------
extern "C" void kernel_launch(void* const* d_in, const int* in_sizes, int n_in,
                              void* d_out, int out_size) {
    const float* x   = (const float*)d_in[0];
    const float* adj = (const float*)d_in[1];
    const float* W   = (const float*)d_in[2];
    const float* a1  = (const float*)d_in[3];
    const float* a2  = (const float*)d_in[4];
    const float* Wo  = (const float*)d_in[5];
    const float* ao1 = (const float*)d_in[6];
    const float* ao2 = (const float*)d_in[7];
    float* out = (float*)d_out;

    static cudaStream_t s2 = nullptr;
    static cudaEvent_t ev_fork = nullptr, ev_join = nullptr;
    if (!s2) {
        cudaStreamCreateWithFlags(&s2, cudaStreamNonBlocking);
        cudaEventCreateWithFlags(&ev_fork, cudaEventDisableTiming);
        cudaEventCreateWithFlags(&ev_join, cudaEventDisableTiming);
        cudaFuncSetAttribute(gemm1_tc,
                             cudaFuncAttributeMaxDynamicSharedMemorySize,
                             SMEM_BYTES);
    }

    // fork: build_csr (pure DRAM) overlaps gemm1 (pure tensor compute)
    cudaEventRecord(ev_fork, 0);
    cudaStreamWaitEvent(s2, ev_fork, 0);
    build_csr_kernel<<<(N * 32 + 255) / 256, 256, 0, s2>>>(adj);
    cudaEventRecord(ev_join, s2);

    dim3 g1(HF / GBN, N / GBM);         // (4, 48)
    gemm1_tc<<<g1, 256, SMEM_BYTES>>>(x, W);
    scores1_kernel<<<(N * H + 255) / 256, 256>>>(a1, a2);

    cudaStreamWaitEvent(0, ev_join, 0);
    agg1_kernel<<<N, 256>>>();

    gemm2_kernel<<<N / G2R, 256>>>(Wo, ao1, ao2);

    agg2_kernel<<<N, 64>>>(out);
}

// round 15
// speedup vs baseline: 1.1664x; 1.1664x over previous
#include <cuda_runtime.h>
#include <cuda_bf16.h>
#include <math.h>

#define N      6144
#define F      512
#define H      4
#define FH     64
#define HF     256   // H*FH
#define C      40
#define MAXD   256
#define ALPHA  0.2f

// ---------------- device scratch ----------------
__device__ float g_Wh1[N * HF];
__device__ float g_f1[H * N];
__device__ float g_f2[H * N];
__device__ float g_h[N * HF];
__device__ int   g_nbr[N * MAXD];
__device__ int   g_deg[N];
__device__ float g_Wh2[N * C];
__device__ float g_f1o[N];
__device__ float g_f2o[N];

// ================= gemm1: Wh1 = x @ Wcat via 3xTF32 tensor-core MMA ======
// Block tile 128x64, 8 warps 4(M)x2(N), warp tile 32x32.
// Register-split tf32 (R7 style) + 2-stage cp.async pipeline for A,
// register-staged prefetch for B.
#define GBM 128
#define GBN 64
#define GBK 32
#define SPAD 36

#define A_WORDS (GBM * SPAD)
#define B_WORDS (GBN * SPAD)
#define SMEM_BYTES ((2 * A_WORDS + 2 * B_WORDS) * 4)

__device__ __forceinline__ void split_tf32(float v, unsigned& hi, unsigned& lo) {
    asm("cvt.rna.tf32.f32 %0, %1;" : "=r"(hi) : "f"(v));
    float r = v - __uint_as_float(hi);
    asm("cvt.rna.tf32.f32 %0, %1;" : "=r"(lo) : "f"(r));
}

#define MMA_TF32(d, a, b)                                                     \
    asm volatile(                                                             \
        "mma.sync.aligned.m16n8k8.row.col.f32.tf32.tf32.f32 "                 \
        "{%0,%1,%2,%3}, {%4,%5,%6,%7}, {%8,%9}, {%0,%1,%2,%3};"               \
        : "+f"(d[0]), "+f"(d[1]), "+f"(d[2]), "+f"(d[3])                      \
        : "r"(a[0]), "r"(a[1]), "r"(a[2]), "r"(a[3]), "r"(b[0]), "r"(b[1]))

#define CP_ASYNC16(saddr, gptr)                                               \
    asm volatile("cp.async.cg.shared.global [%0], [%1], 16;"                  \
                 :: "r"(saddr), "l"(gptr))
#define CP_COMMIT() asm volatile("cp.async.commit_group;" ::: "memory")
#define CP_WAIT0()  asm volatile("cp.async.wait_group 0;" ::: "memory")

__global__ __launch_bounds__(256) void gemm1_tc(const float* __restrict__ x,
                                                const float* __restrict__ W) {
    extern __shared__ float dsm[];
    float* Asm[2] = {dsm, dsm + A_WORDS};
    float* Bsm[2] = {dsm + 2 * A_WORDS, dsm + 2 * A_WORDS + B_WORDS};

    const int tid = threadIdx.x;
    const int wid = tid >> 5, lane = tid & 31;
    const int group = lane >> 2, tig = lane & 3;
    const int warp_m = wid >> 1, warp_n = wid & 1;
    const int row0 = blockIdx.y * GBM;
    const int col0 = blockIdx.x * GBN;
    const float* Wb = W + (col0 >> 6) * (F * FH);

    // per-thread load coordinates
    const int am = tid >> 1;                 // A: 2 float4 per thread? no:
    // A tile = 128 rows x 32 k = 1024 float4 -> 4 per thread
    const int a_m[4] = { (tid + 0) >> 3, (tid + 256) >> 3,
                         (tid + 512) >> 3, (tid + 768) >> 3 };
    const int a_q = tid & 7;
    // B tile = 32 k x 64 c = 512 float4 -> 2 per thread
    const int b_k0 = tid >> 4;               // 0..15 (first), +16 second
    const int b_cq = tid & 15;

    float acc[2][4][4];
#pragma unroll
    for (int mt = 0; mt < 2; mt++)
#pragma unroll
        for (int nt = 0; nt < 4; nt++)
#pragma unroll
            for (int j = 0; j < 4; j++) acc[mt][nt][j] = 0.f;

    (void)am;

    // ---- prologue: stage 0 ----
    {
        unsigned sa = (unsigned)__cvta_generic_to_shared(Asm[0]);
#pragma unroll
        for (int it = 0; it < 4; it++) {
            int m = a_m[it];
            CP_ASYNC16(sa + (m * SPAD + a_q * 4) * 4,
                       &x[(row0 + m) * F + a_q * 4]);
        }
        CP_COMMIT();
        float4 b0 = *(const float4*)&Wb[b_k0 * FH + b_cq * 4];
        float4 b1 = *(const float4*)&Wb[(b_k0 + 16) * FH + b_cq * 4];
        CP_WAIT0();
        float* B = Bsm[0];
        B[(b_cq * 4 + 0) * SPAD + b_k0] = b0.x;
        B[(b_cq * 4 + 1) * SPAD + b_k0] = b0.y;
        B[(b_cq * 4 + 2) * SPAD + b_k0] = b0.z;
        B[(b_cq * 4 + 3) * SPAD + b_k0] = b0.w;
        B[(b_cq * 4 + 0) * SPAD + b_k0 + 16] = b1.x;
        B[(b_cq * 4 + 1) * SPAD + b_k0 + 16] = b1.y;
        B[(b_cq * 4 + 2) * SPAD + b_k0 + 16] = b1.z;
        B[(b_cq * 4 + 3) * SPAD + b_k0 + 16] = b1.w;
        __syncthreads();
    }

    for (int k0 = 0; k0 < F; k0 += GBK) {
        const int cur = (k0 >> 5) & 1, nxt = cur ^ 1;
        const bool more = (k0 + GBK) < F;
        float4 b0, b1;
        if (more) {
            unsigned sa = (unsigned)__cvta_generic_to_shared(Asm[nxt]);
#pragma unroll
            for (int it = 0; it < 4; it++) {
                int m = a_m[it];
                CP_ASYNC16(sa + (m * SPAD + a_q * 4) * 4,
                           &x[(row0 + m) * F + k0 + GBK + a_q * 4]);
            }
            CP_COMMIT();
            b0 = *(const float4*)&Wb[(k0 + GBK + b_k0) * FH + b_cq * 4];
            b1 = *(const float4*)&Wb[(k0 + GBK + b_k0 + 16) * FH + b_cq * 4];
        }

        const float* As = Asm[cur];
        const float* Bs = Bsm[cur];
#pragma unroll
        for (int kk = 0; kk < 4; kk++) {
            const int kb = kk * 8;
            unsigned ahi[2][4], alo[2][4];
#pragma unroll
            for (int mt = 0; mt < 2; mt++) {
                int r0i = (warp_m * 32 + mt * 16 + group) * SPAD + kb + tig;
                int r1i = r0i + 8 * SPAD;
                split_tf32(As[r0i],     ahi[mt][0], alo[mt][0]);
                split_tf32(As[r1i],     ahi[mt][1], alo[mt][1]);
                split_tf32(As[r0i + 4], ahi[mt][2], alo[mt][2]);
                split_tf32(As[r1i + 4], ahi[mt][3], alo[mt][3]);
            }
            unsigned bhi[4][2], blo[4][2];
#pragma unroll
            for (int nt = 0; nt < 4; nt++) {
                int ni = (warp_n * 32 + nt * 8 + group) * SPAD + kb + tig;
                split_tf32(Bs[ni],     bhi[nt][0], blo[nt][0]);
                split_tf32(Bs[ni + 4], bhi[nt][1], blo[nt][1]);
            }
#pragma unroll
            for (int mt = 0; mt < 2; mt++)
#pragma unroll
                for (int nt = 0; nt < 4; nt++) {
                    MMA_TF32(acc[mt][nt], ahi[mt], bhi[nt]);
                    MMA_TF32(acc[mt][nt], alo[mt], bhi[nt]);
                    MMA_TF32(acc[mt][nt], ahi[mt], blo[nt]);
                }
        }

        if (more) {
            CP_WAIT0();
            float* B = Bsm[nxt];
            B[(b_cq * 4 + 0) * SPAD + b_k0] = b0.x;
            B[(b_cq * 4 + 1) * SPAD + b_k0] = b0.y;
            B[(b_cq * 4 + 2) * SPAD + b_k0] = b0.z;
            B[(b_cq * 4 + 3) * SPAD + b_k0] = b0.w;
            B[(b_cq * 4 + 0) * SPAD + b_k0 + 16] = b1.x;
            B[(b_cq * 4 + 1) * SPAD + b_k0 + 16] = b1.y;
            B[(b_cq * 4 + 2) * SPAD + b_k0 + 16] = b1.z;
            B[(b_cq * 4 + 3) * SPAD + b_k0 + 16] = b1.w;
        }
        __syncthreads();
    }

#pragma unroll
    for (int mt = 0; mt < 2; mt++)
#pragma unroll
        for (int nt = 0; nt < 4; nt++) {
            int r = row0 + warp_m * 32 + mt * 16 + group;
            int cc = col0 + warp_n * 32 + nt * 8 + tig * 2;
            float2 v0 = {acc[mt][nt][0], acc[mt][nt][1]};
            float2 v1 = {acc[mt][nt][2], acc[mt][nt][3]};
            *(float2*)&g_Wh1[r * HF + cc] = v0;
            *(float2*)&g_Wh1[(r + 8) * HF + cc] = v1;
        }
}

// ---------------- scores1 ------------------------------------------------
__global__ void scores1_kernel(const float* __restrict__ a1,
                               const float* __restrict__ a2) {
    int idx = blockIdx.x * blockDim.x + threadIdx.x;
    if (idx >= N * H) return;
    int i = idx >> 2;
    int h = idx & 3;
    const float* wh = &g_Wh1[i * HF + h * FH];
    float s1 = 0.f, s2 = 0.f;
#pragma unroll
    for (int c = 0; c < FH; c++) {
        float v = wh[c];
        s1 += v * a1[h * FH + c];
        s2 += v * a2[h * FH + c];
    }
    g_f1[h * N + i] = s1;
    g_f2[h * N + i] = s2;
}

// ---------------- build CSR ----------------------------------------------
__global__ void build_csr_kernel(const float* __restrict__ adj) {
    int warp = (blockIdx.x * blockDim.x + threadIdx.x) >> 5;
    int lane = threadIdx.x & 31;
    if (warp >= N) return;
    const float* row = adj + (long long)warp * N;
    int cnt = 0;
    for (int j0 = 0; j0 < N; j0 += 32) {
        float v = row[j0 + lane];
        unsigned m = __ballot_sync(0xffffffffu, v > 0.f);
        if (v > 0.f) {
            int pre = __popc(m & ((1u << lane) - 1u));
            int slot = cnt + pre;
            if (slot < MAXD) g_nbr[warp * MAXD + slot] = j0 + lane;
        }
        cnt += __popc(m);
    }
    if (lane == 0) g_deg[warp] = cnt < MAXD ? cnt : MAXD;
}

// ---------------- agg1: layer-1 softmax aggregation + ELU ----------------
__global__ __launch_bounds__(256) void agg1_kernel(void) {
    const int i = blockIdx.x;
    const int t = threadIdx.x;
    const int h = t >> 6, c = t & 63;
    const int lane = t & 31;
    const int half = (t >> 5) & 1;

    __shared__ int   s_nbr[MAXD];
    __shared__ float s_w[H][MAXD];
    __shared__ float s_red[H][2];
    __shared__ float s_sum[H][2];
    __shared__ float s_sumf[H];
    __shared__ float s_part[4 * HF];

    const int deg = g_deg[i];
    for (int k = t; k < deg; k += 256) s_nbr[k] = g_nbr[i * MAXD + k];
    __syncthreads();

    const float f1 = g_f1[h * N + i];

    float lmax = -3.0e38f;
    for (int k = c; k < deg; k += 64) {
        float s = f1 + g_f2[h * N + s_nbr[k]];
        s = s > 0.f ? s : ALPHA * s;
        s_w[h][k] = s;
        lmax = fmaxf(lmax, s);
    }
#pragma unroll
    for (int o = 16; o > 0; o >>= 1)
        lmax = fmaxf(lmax, __shfl_xor_sync(0xffffffffu, lmax, o));
    if (lane == 0) s_red[h][half] = lmax;
    __syncthreads();
    const float mx = fmaxf(s_red[h][0], s_red[h][1]);

    float lsum = 0.f;
    for (int k = c; k < deg; k += 64) {
        float w = expf(s_w[h][k] - mx);
        s_w[h][k] = w;
        lsum += w;
    }
#pragma unroll
    for (int o = 16; o > 0; o >>= 1)
        lsum += __shfl_xor_sync(0xffffffffu, lsum, o);
    if (lane == 0) s_sum[h][half] = lsum;
    __syncthreads();
    if (c == 0) s_sumf[h] = s_sum[h][0] + s_sum[h][1];

    // gather: group g handles neighbors k = g, g+4, ... with float4 loads
    const int g = t >> 6;
    const int u = t & 63;
    const int h2 = u >> 4;
    float ax = 0.f, ay = 0.f, az = 0.f, aw = 0.f;
#pragma unroll 4
    for (int k = g; k < deg; k += 4) {
        float w = s_w[h2][k];
        float4 v = __ldg((const float4*)(g_Wh1 + s_nbr[k] * HF) + u);
        ax += w * v.x; ay += w * v.y; az += w * v.z; aw += w * v.w;
    }
    s_part[g * HF + 0 * 64 + u] = ax;
    s_part[g * HF + 1 * 64 + u] = ay;
    s_part[g * HF + 2 * 64 + u] = az;
    s_part[g * HF + 3 * 64 + u] = aw;
    __syncthreads();

    const int cu = t >> 2, cj = t & 3;
    float v = s_part[0 * HF + cj * 64 + cu] + s_part[1 * HF + cj * 64 + cu] +
              s_part[2 * HF + cj * 64 + cu] + s_part[3 * HF + cj * 64 + cu];
    v /= s_sumf[t >> 6];
    v = v > 0.f ? v : expm1f(v);
    g_h[i * HF + t] = v;
}

// ------- gemm2 + scores2 fused ------------------------------------------
#define G2R 32
__global__ __launch_bounds__(256) void gemm2_kernel(const float* __restrict__ Wo,
                                                    const float* __restrict__ ao1,
                                                    const float* __restrict__ ao2) {
    __shared__ float sh[G2R][HF + 4];
    __shared__ float s_o[G2R][C + 4];
    const int i0 = blockIdx.x * G2R;
    const int tid = threadIdx.x;

#pragma unroll
    for (int it = 0; it < 8; it++) {
        int idx = tid + it * 256;
        int r = idx >> 6, kq = idx & 63;
        float4 v = *(const float4*)&g_h[(i0 + r) * HF + kq * 4];
        *(float4*)&sh[r][kq * 4] = v;
    }
    __syncthreads();

    if (tid < 160) {
        int cc = tid % 40;
        int rg = tid / 40;
        float acc[8];
#pragma unroll
        for (int j = 0; j < 8; j++) acc[j] = 0.f;
        for (int k = 0; k < HF; k++) {
            float wv = __ldg(&Wo[k * C + cc]);
#pragma unroll
            for (int j = 0; j < 8; j++)
                acc[j] += wv * sh[rg * 8 + j][k];
        }
#pragma unroll
        for (int j = 0; j < 8; j++) {
            g_Wh2[(i0 + rg * 8 + j) * C + cc] = acc[j];
            s_o[rg * 8 + j][cc] = acc[j];
        }
    }
    __syncthreads();

    if (tid < G2R) {
        float s1 = 0.f, s2 = 0.f;
#pragma unroll
        for (int cc = 0; cc < C; cc++) {
            float v = s_o[tid][cc];
            s1 += v * ao1[cc];
            s2 += v * ao2[cc];
        }
        g_f1o[i0 + tid] = s1;
        g_f2o[i0 + tid] = s2;
    }
}

// -------- agg2: layer-2 aggregation + ELU + log_softmax ------------------
__global__ __launch_bounds__(64) void agg2_kernel(float* __restrict__ out) {
    const int i = blockIdx.x;
    const int t = threadIdx.x;
    const int lane = t & 31, w = t >> 5;
    __shared__ int   s_nbr[MAXD];
    __shared__ float s_w[MAXD];
    __shared__ float s_r[2];
    __shared__ float red[64];

    const int deg = g_deg[i];
    const float f1 = g_f1o[i];

    float lmax = -3.0e38f;
    for (int k = t; k < deg; k += 64) {
        int j = g_nbr[i * MAXD + k];
        s_nbr[k] = j;
        float s = f1 + g_f2o[j];
        s = s > 0.f ? s : ALPHA * s;
        s_w[k] = s;
        lmax = fmaxf(lmax, s);
    }
#pragma unroll
    for (int o = 16; o > 0; o >>= 1)
        lmax = fmaxf(lmax, __shfl_xor_sync(0xffffffffu, lmax, o));
    if (lane == 0) s_r[w] = lmax;
    __syncthreads();
    const float mx = fmaxf(s_r[0], s_r[1]);

    float lsum = 0.f;
    for (int k = t; k < deg; k += 64) {
        float e = expf(s_w[k] - mx);
        s_w[k] = e;
        lsum += e;
    }
#pragma unroll
    for (int o = 16; o > 0; o >>= 1)
        lsum += __shfl_xor_sync(0xffffffffu, lsum, o);
    __syncthreads();
    if (lane == 0) s_r[w] = lsum;
    __syncthreads();
    const float sum = s_r[0] + s_r[1];

    float acc = 0.f;
    if (t < C) {
        for (int k = 0; k < deg; k++)
            acc += s_w[k] * g_Wh2[s_nbr[k] * C + t];
    }
    float v = acc / sum;
    v = v > 0.f ? v : expm1f(v);

    red[t] = (t < C) ? v : -3.0e38f;
    __syncthreads();
#pragma unroll
    for (int s = 32; s > 0; s >>= 1) {
        if (t < s) red[t] = fmaxf(red[t], red[t + s]);
        __syncthreads();
    }
    float m2 = red[0];
    __syncthreads();
    red[t] = (t < C) ? expf(v - m2) : 0.f;
    __syncthreads();
#pragma unroll
    for (int s = 32; s > 0; s >>= 1) {
        if (t < s) red[t] += red[t + s];
        __syncthreads();
    }
    float lse = m2 + logf(red[0]);
    if (t < C) out[i * C + t] = v - lse;
}

// ---------------- launch ---------------------------------------------------
extern "C" void kernel_launch(void* const* d_in, const int* in_sizes, int n_in,
                              void* d_out, int out_size) {
    const float* x   = (const float*)d_in[0];
    const float* adj = (const float*)d_in[1];
    const float* W   = (const float*)d_in[2];
    const float* a1  = (const float*)d_in[3];
    const float* a2  = (const float*)d_in[4];
    const float* Wo  = (const float*)d_in[5];
    const float* ao1 = (const float*)d_in[6];
    const float* ao2 = (const float*)d_in[7];
    float* out = (float*)d_out;

    static cudaStream_t s2 = nullptr;
    static cudaEvent_t ev_fork = nullptr, ev_join = nullptr;
    if (!s2) {
        cudaStreamCreateWithFlags(&s2, cudaStreamNonBlocking);
        cudaEventCreateWithFlags(&ev_fork, cudaEventDisableTiming);
        cudaEventCreateWithFlags(&ev_join, cudaEventDisableTiming);
        cudaFuncSetAttribute(gemm1_tc,
                             cudaFuncAttributeMaxDynamicSharedMemorySize,
                             SMEM_BYTES);
    }

    // fork: build_csr (pure DRAM) overlaps gemm1 (pure tensor compute)
    cudaEventRecord(ev_fork, 0);
    cudaStreamWaitEvent(s2, ev_fork, 0);
    build_csr_kernel<<<(N * 32 + 255) / 256, 256, 0, s2>>>(adj);
    cudaEventRecord(ev_join, s2);

    dim3 g1(HF / GBN, N / GBM);         // (4, 48)
    gemm1_tc<<<g1, 256, SMEM_BYTES>>>(x, W);
    scores1_kernel<<<(N * H + 255) / 256, 256>>>(a1, a2);

    cudaStreamWaitEvent(0, ev_join, 0);
    agg1_kernel<<<N, 256>>>();

    gemm2_kernel<<<N / G2R, 256>>>(Wo, ao1, ao2);

    agg2_kernel<<<N, 64>>>(out);
}